// round 2
// baseline (speedup 1.0000x reference)
#include <cuda_runtime.h>
#include <cuda_bf16.h>
#include <cstdint>
#include <cstddef>

// ----------------------------------------------------------------------------
// FocalTransformerBlock  B=2, H=W=256, C=128, HEADS=4, HD=32, WS=8, EXP=3
// NWH=32, WA=64, N_ROLLED=220, N_ALL=229 (padded to 232 in-kernel)
// ----------------------------------------------------------------------------

#define BATCH   2
#define HW      65536           // 256*256
#define CDIM    128
#define MROWS   (BATCH*HW)      // 131072
#define NWH     32
#define NWIN    (NWH*NWH)       // 1024 per batch
#define WA      64
#define NROLL   220
#define NALL    229
#define NPAD    232
#define HEADS   4
#define HD      32
#define SCALE   0.17677669529663687f   // 32^-0.5

// -------------------------- scratch (static device) -------------------------
__device__ float g_xh[MROWS * CDIM];          // LN output (reused for LN2)
__device__ float g_qkv[MROWS * 3 * CDIM];     // qkv of full map
__device__ float g_pooled[BATCH * NWIN * CDIM];
__device__ float g_qkvp[BATCH * NWIN * 3 * CDIM];
__device__ float g_attnout[MROWS * CDIM];
__device__ float g_x2[MROWS * CDIM];          // after first residual
__device__ float g_fc1[MROWS * 512];
__device__ int   g_rolled[156];

__constant__ int c_sh[4] = {-3,-3, 3, 3};
__constant__ int c_sw[4] = {-3, 3,-3, 3};

// -------------------------- init rolled index table -------------------------
__global__ void init_rolled_kernel() {
    if (threadIdx.x == 0 && blockIdx.x == 0) {
        int cnt = 0;
        for (int idx = 0; idx < 256; idx++) {
            int m = idx >> 6, r = (idx >> 3) & 7, c = idx & 7;
            bool valid;
            if      (m == 0) valid = (r >= 5) || (c >= 5);
            else if (m == 1) valid = (r >= 5) || (c < 3);
            else if (m == 2) valid = (r < 3)  || (c >= 5);
            else             valid = (r < 3)  || (c < 3);
            if (valid) g_rolled[cnt++] = idx;
        }
    }
}

// -------------------------- layernorm (warp per row) -------------------------
__global__ void __launch_bounds__(256) ln_kernel(
    const float* __restrict__ x, const float* __restrict__ g,
    const float* __restrict__ b, float* __restrict__ out, int rows)
{
    int row = (blockIdx.x * blockDim.x + threadIdx.x) >> 5;
    if (row >= rows) return;
    int lane = threadIdx.x & 31;
    const float4* xr = (const float4*)(x + (size_t)row * CDIM);
    float4 v = xr[lane];
    float s = v.x + v.y + v.z + v.w;
    #pragma unroll
    for (int o = 16; o > 0; o >>= 1) s += __shfl_xor_sync(~0u, s, o);
    float mu = s * (1.0f / CDIM);
    float dx = v.x-mu, dy = v.y-mu, dz = v.z-mu, dw = v.w-mu;
    float s2 = dx*dx + dy*dy + dz*dz + dw*dw;
    #pragma unroll
    for (int o = 16; o > 0; o >>= 1) s2 += __shfl_xor_sync(~0u, s2, o);
    float rs = rsqrtf(s2 * (1.0f / CDIM) + 1e-5f);
    float4 gg = ((const float4*)g)[lane];
    float4 bb = ((const float4*)b)[lane];
    float4 o4;
    o4.x = dx*rs*gg.x + bb.x;
    o4.y = dy*rs*gg.y + bb.y;
    o4.z = dz*rs*gg.z + bb.z;
    o4.w = dw*rs*gg.w + bb.w;
    ((float4*)(out + (size_t)row * CDIM))[lane] = o4;
}

// -------------------------- SGEMM: out = A @ W^T + bias  (+epilogue) --------
// A: (M,K) row-major, W: (N,K) row-major, out: (M,N)
// epi: 0=none, 1=exact gelu, 2=add residual
__global__ void __launch_bounds__(256) gemm_kernel(
    const float* __restrict__ A, const float* __restrict__ W,
    const float* __restrict__ bias, const float* __restrict__ res,
    float* __restrict__ out, int M, int N, int K, int epi)
{
    __shared__ float As[16][68];
    __shared__ float Ws[16][68];
    int tid = threadIdx.x;
    int tx = tid & 15, ty = tid >> 4;
    int m0 = blockIdx.y * 64, n0 = blockIdx.x * 64;
    float acc[4][4];
    #pragma unroll
    for (int i = 0; i < 4; i++)
        #pragma unroll
        for (int j = 0; j < 4; j++) acc[i][j] = 0.f;

    for (int k0 = 0; k0 < K; k0 += 16) {
        #pragma unroll
        for (int i = 0; i < 4; i++) {
            int l = tid + i * 256;
            int mm = l >> 4, kk = l & 15;
            As[kk][mm] = A[(size_t)(m0 + mm) * K + k0 + kk];
            Ws[kk][mm] = W[(size_t)(n0 + mm) * K + k0 + kk];
        }
        __syncthreads();
        #pragma unroll
        for (int kk = 0; kk < 16; kk++) {
            float4 a4 = *(const float4*)&As[kk][ty * 4];
            float4 b4 = *(const float4*)&Ws[kk][tx * 4];
            float av[4] = {a4.x, a4.y, a4.z, a4.w};
            float bv[4] = {b4.x, b4.y, b4.z, b4.w};
            #pragma unroll
            for (int i = 0; i < 4; i++)
                #pragma unroll
                for (int j = 0; j < 4; j++)
                    acc[i][j] += av[i] * bv[j];
        }
        __syncthreads();
    }

    #pragma unroll
    for (int i = 0; i < 4; i++) {
        int row = m0 + ty * 4 + i;
        #pragma unroll
        for (int j = 0; j < 4; j++) {
            int col = n0 + tx * 4 + j;
            float v = acc[i][j] + bias[col];
            if (epi == 1) {
                v = 0.5f * v * (1.0f + erff(v * 0.70710678118654752f));
            } else if (epi == 2) {
                v += res[(size_t)row * N + col];
            }
            out[(size_t)row * N + col] = v;
        }
    }
}

// -------------------------- window pooling ----------------------------------
__global__ void __launch_bounds__(128) pool_kernel(
    const float* __restrict__ xh, const float* __restrict__ pw,
    const float* __restrict__ pb, float* __restrict__ pooled)
{
    int w = blockIdx.x;                 // b*1024 + i*32 + j
    int b = w >> 10, ij = w & 1023;
    int i = ij >> 5, j = ij & 31;
    int c = threadIdx.x;
    float acc = 0.f;
    #pragma unroll
    for (int n = 0; n < 64; n++) {
        int r = n >> 3, cc = n & 7;
        size_t tok = (size_t)(b * HW + (i * 8 + r) * 256 + (j * 8 + cc));
        acc += xh[tok * CDIM + c] * pw[n];
    }
    pooled[(size_t)w * CDIM + c] = acc + pb[0];
}

// -------------------------- attention ----------------------------------------
// grid: (2048 windows, 4 heads), 512 threads
// smem: Qt[32][68] | Kt[32][236] | V[232][32] | Attn[64][232] | inv[64]
__global__ void __launch_bounds__(512) attn_kernel(
    const float* __restrict__ qkv, const float* __restrict__ qkvp,
    const float* __restrict__ rpbt, const float* __restrict__ rpbn,
    const float* __restrict__ rpbw, float* __restrict__ out)
{
    extern __shared__ float sm[];
    float* sQt   = sm;                 // 32*68  = 2176
    float* sKt   = sQt + 2176;         // 32*236 = 7552
    float* sV    = sKt + 7552;         // 232*32 = 7424
    float* sAttn = sV + 7424;          // 64*232 = 14848
    float* sInv  = sAttn + 14848;      // 64

    int tid = threadIdx.x;
    int w = blockIdx.x, h = blockIdx.y;
    int b = w >> 10, wi = (w >> 5) & 31, wj = w & 31;
    int bt = b << 16;                  // b * 65536

    // ---- load Q (scaled), transposed: sQt[d][q] ----
    for (int t = tid; t < WA * HD; t += 512) {
        int q = t >> 5, d = t & 31;
        int gi = wi * 8 + (q >> 3), gj = wj * 8 + (q & 7);
        sQt[d * 68 + q] = qkv[(size_t)(bt + gi * 256 + gj) * 384 + h * 32 + d] * SCALE;
    }
    // ---- gather K_all (transposed), V_all ; pad rows 229..231 with zero ----
    for (int t = tid; t < NPAD * HD; t += 512) {
        int krow = t >> 5, d = t & 31;
        float kval = 0.f, vval = 0.f;
        if (krow < NROLL) {
            int gi, gj;
            if (krow < 64) {
                gi = wi * 8 + (krow >> 3);
                gj = wj * 8 + (krow & 7);
            } else {
                int raw = g_rolled[krow - 64];
                int m = raw >> 6, r = (raw >> 3) & 7, c = raw & 7;
                gi = (wi * 8 + r - c_sh[m]) & 255;
                gj = (wj * 8 + c - c_sw[m]) & 255;
            }
            size_t base = (size_t)(bt + gi * 256 + gj) * 384 + 128 + h * 32 + d;
            kval = qkv[base];
            vval = qkv[base + 128];
        } else if (krow < NALL) {
            int p = krow - NROLL;
            int pi = wi + p / 3 - 1, pj = wj + p % 3 - 1;
            if (pi >= 0 && pi < 32 && pj >= 0 && pj < 32) {
                size_t base = (size_t)((b << 10) + pi * 32 + pj) * 384 + 128 + h * 32 + d;
                kval = qkvp[base];
                vval = qkvp[base + 128];
            }
        }
        sKt[d * 236 + krow] = kval;
        sV[krow * 32 + d]   = vval;
    }
    // ---- init scores with bias + pool mask (cols 0..228) ----
    for (int t = tid; t < WA * NALL; t += 512) {
        int q = t / NALL, k = t % NALL;
        int qr = q >> 3, qc = q & 7;
        float bias;
        if (k < 64) {
            int kr = k >> 3, kc = k & 7;
            bias = rpbt[((qr - kr + 7) * 15 + (qc - kc + 7)) * HEADS + h];
        } else if (k < NROLL) {
            bias = rpbn[(size_t)(h * 64 + q) * 156 + (k - 64)];
        } else {
            int p = k - NROLL;
            int kr = p / 3, kc = p % 3;
            bias = rpbw[h * 100 + (qr - kr + 2) * 10 + (qc - kc + 2)];
            int pi = wi + kr - 1, pj = wj + kc - 1;
            if (!(pi >= 0 && pi < 32 && pj >= 0 && pj < 32)) bias -= 100.f;
        }
        sAttn[q * NPAD + k] = bias;
    }
    __syncthreads();

    // ---- QK^T: 4q x 4k register tiles (16 qg x 58 kg = 928 tiles) ----
    for (int tt = tid; tt < 16 * 58; tt += 512) {
        int kg = tt % 58, qg = tt / 58;
        int k0 = kg * 4, q0 = qg * 4;
        float a00=0,a01=0,a02=0,a03=0, a10=0,a11=0,a12=0,a13=0;
        float a20=0,a21=0,a22=0,a23=0, a30=0,a31=0,a32=0,a33=0;
        #pragma unroll
        for (int d = 0; d < 32; d++) {
            float4 qv = *(const float4*)&sQt[d * 68 + q0];
            float4 kv = *(const float4*)&sKt[d * 236 + k0];
            a00 += qv.x*kv.x; a01 += qv.x*kv.y; a02 += qv.x*kv.z; a03 += qv.x*kv.w;
            a10 += qv.y*kv.x; a11 += qv.y*kv.y; a12 += qv.y*kv.z; a13 += qv.y*kv.w;
            a20 += qv.z*kv.x; a21 += qv.z*kv.y; a22 += qv.z*kv.z; a23 += qv.z*kv.w;
            a30 += qv.w*kv.x; a31 += qv.w*kv.y; a32 += qv.w*kv.z; a33 += qv.w*kv.w;
        }
        float4* p0 = (float4*)&sAttn[(q0+0) * NPAD + k0];
        float4* p1 = (float4*)&sAttn[(q0+1) * NPAD + k0];
        float4* p2 = (float4*)&sAttn[(q0+2) * NPAD + k0];
        float4* p3 = (float4*)&sAttn[(q0+3) * NPAD + k0];
        float4 c0 = *p0, c1 = *p1, c2 = *p2, c3 = *p3;
        c0.x+=a00; c0.y+=a01; c0.z+=a02; c0.w+=a03; *p0 = c0;
        c1.x+=a10; c1.y+=a11; c1.z+=a12; c1.w+=a13; *p1 = c1;
        c2.x+=a20; c2.y+=a21; c2.z+=a22; c2.w+=a23; *p2 = c2;
        c3.x+=a30; c3.y+=a31; c3.z+=a32; c3.w+=a33; *p3 = c3;
    }
    __syncthreads();

    // ---- softmax: 8 threads per row; zero pad cols 229..231 ----
    {
        int row = tid >> 3, l8 = tid & 7;
        float* pr = sAttn + row * NPAD;
        float mx = -1e30f;
        for (int k = l8; k < NALL; k += 8) mx = fmaxf(mx, pr[k]);
        mx = fmaxf(mx, __shfl_xor_sync(~0u, mx, 1));
        mx = fmaxf(mx, __shfl_xor_sync(~0u, mx, 2));
        mx = fmaxf(mx, __shfl_xor_sync(~0u, mx, 4));
        float s = 0.f;
        for (int k = l8; k < NALL; k += 8) {
            float e = __expf(pr[k] - mx);
            pr[k] = e;
            s += e;
        }
        s += __shfl_xor_sync(~0u, s, 1);
        s += __shfl_xor_sync(~0u, s, 2);
        s += __shfl_xor_sync(~0u, s, 4);
        if (l8 == 0) sInv[row] = 1.0f / s;
        if (l8 < 3) pr[NALL + l8] = 0.f;
    }
    __syncthreads();

    // ---- P @ V: 1q x 4d per thread, k unrolled by 4 ----
    {
        int q = tid >> 3, d0 = (tid & 7) * 4;
        const float* pr = sAttn + q * NPAD;
        float a0=0.f, a1=0.f, a2=0.f, a3=0.f;
        #pragma unroll 2
        for (int k = 0; k < NPAD; k += 4) {
            float4 pv = *(const float4*)&pr[k];
            float4 v0 = *(const float4*)&sV[(k+0) * 32 + d0];
            float4 v1 = *(const float4*)&sV[(k+1) * 32 + d0];
            float4 v2 = *(const float4*)&sV[(k+2) * 32 + d0];
            float4 v3 = *(const float4*)&sV[(k+3) * 32 + d0];
            a0 += pv.x*v0.x + pv.y*v1.x + pv.z*v2.x + pv.w*v3.x;
            a1 += pv.x*v0.y + pv.y*v1.y + pv.z*v2.y + pv.w*v3.y;
            a2 += pv.x*v0.z + pv.y*v1.z + pv.z*v2.z + pv.w*v3.z;
            a3 += pv.x*v0.w + pv.y*v1.w + pv.z*v2.w + pv.w*v3.w;
        }
        float inv = sInv[q];
        int gi = wi * 8 + (q >> 3), gj = wj * 8 + (q & 7);
        float* o = out + (size_t)(bt + gi * 256 + gj) * CDIM + h * 32 + d0;
        *(float4*)o = make_float4(a0 * inv, a1 * inv, a2 * inv, a3 * inv);
    }
}

// ----------------------------------------------------------------------------
extern "C" void kernel_launch(void* const* d_in, const int* in_sizes, int n_in,
                              void* d_out, int out_size)
{
    const float* x      = (const float*)d_in[0];
    const float* qkv_w  = (const float*)d_in[1];
    const float* qkv_b  = (const float*)d_in[2];
    const float* proj_w = (const float*)d_in[3];
    const float* proj_b = (const float*)d_in[4];
    const float* n1g    = (const float*)d_in[5];
    const float* n1b    = (const float*)d_in[6];
    const float* n2g    = (const float*)d_in[7];
    const float* n2b    = (const float*)d_in[8];
    const float* rpbt   = (const float*)d_in[9];
    const float* rpbn   = (const float*)d_in[10];
    const float* rpbw   = (const float*)d_in[11];
    const float* poolw  = (const float*)d_in[12];
    const float* poolb  = (const float*)d_in[13];
    const float* fc1_w  = (const float*)d_in[14];
    const float* fc1_b  = (const float*)d_in[15];
    const float* fc2_w  = (const float*)d_in[16];
    const float* fc2_b  = (const float*)d_in[17];
    float* outp = (float*)d_out;

    float *p_xh, *p_qkv, *p_pooled, *p_qkvp, *p_attnout, *p_x2, *p_fc1;
    cudaGetSymbolAddress((void**)&p_xh, g_xh);
    cudaGetSymbolAddress((void**)&p_qkv, g_qkv);
    cudaGetSymbolAddress((void**)&p_pooled, g_pooled);
    cudaGetSymbolAddress((void**)&p_qkvp, g_qkvp);
    cudaGetSymbolAddress((void**)&p_attnout, g_attnout);
    cudaGetSymbolAddress((void**)&p_x2, g_x2);
    cudaGetSymbolAddress((void**)&p_fc1, g_fc1);

    const int ATTN_SMEM = (2176 + 7552 + 7424 + 14848 + 64) * 4;  // 128256 B
    cudaFuncSetAttribute(attn_kernel,
                         cudaFuncAttributeMaxDynamicSharedMemorySize, ATTN_SMEM);

    // 0. rolled index table
    init_rolled_kernel<<<1, 32>>>();
    // 1. LN1
    ln_kernel<<<MROWS / 8, 256>>>(x, n1g, n1b, p_xh, MROWS);
    // 2. qkv GEMM  (131072 x 384, K=128)
    gemm_kernel<<<dim3(384 / 64, MROWS / 64), 256>>>(
        p_xh, qkv_w, qkv_b, nullptr, p_qkv, MROWS, 384, 128, 0);
    // 3. window pooling (B,32,32,C)
    pool_kernel<<<BATCH * NWIN, 128>>>(p_xh, poolw, poolb, p_pooled);
    // 4. qkv of pooled (2048 x 384, K=128)
    gemm_kernel<<<dim3(384 / 64, (BATCH * NWIN) / 64), 256>>>(
        p_pooled, qkv_w, qkv_b, nullptr, p_qkvp, BATCH * NWIN, 384, 128, 0);
    // 5. focal attention
    attn_kernel<<<dim3(BATCH * NWIN, HEADS), 512, ATTN_SMEM>>>(
        p_qkv, p_qkvp, rpbt, rpbn, rpbw, p_attnout);
    // 6. proj + residual(x)
    gemm_kernel<<<dim3(CDIM / 64, MROWS / 64), 256>>>(
        p_attnout, proj_w, proj_b, x, p_x2, MROWS, CDIM, 128, 2);
    // 7. LN2
    ln_kernel<<<MROWS / 8, 256>>>(p_x2, n2g, n2b, p_xh, MROWS);
    // 8. fc1 + exact GELU (131072 x 512, K=128)
    gemm_kernel<<<dim3(512 / 64, MROWS / 64), 256>>>(
        p_xh, fc1_w, fc1_b, nullptr, p_fc1, MROWS, 512, 128, 1);
    // 9. fc2 + residual(x2) -> out (131072 x 128, K=512)
    gemm_kernel<<<dim3(CDIM / 64, MROWS / 64), 256>>>(
        p_fc1, fc2_w, fc2_b, p_x2, outp, MROWS, CDIM, 512, 2);
}

// round 4
// speedup vs baseline: 2.4391x; 2.4391x over previous
#include <cuda_runtime.h>
#include <cuda_bf16.h>
#include <cstdint>
#include <cstddef>

// ----------------------------------------------------------------------------
// FocalTransformerBlock  B=2, H=W=256, C=128, HEADS=4, HD=32, WS=8, EXP=3
// tf32 tensor-core version (mma.sync.m16n8k8)
// ----------------------------------------------------------------------------

#define BATCH   2
#define HW      65536
#define CDIM    128
#define MROWS   (BATCH*HW)      // 131072
#define NWH     32
#define NWIN    1024
#define WA      64
#define NROLL   220
#define NALL    229
#define NPAD    256             // K-dim padded for mma
#define LDP     260             // row stride of P / Vt (conflict-free)
#define HEADS   4
#define HD      32
#define SCALE   0.17677669529663687f

// -------------------------- scratch (static device) -------------------------
__device__ float g_xh[MROWS * CDIM];
__device__ float g_qkv[MROWS * 3 * CDIM];
__device__ float g_pooled[BATCH * NWIN * CDIM];
__device__ float g_qkvp[BATCH * NWIN * 3 * CDIM];
__device__ float g_attnout[MROWS * CDIM];
__device__ float g_x2[MROWS * CDIM];
__device__ float g_fc1[MROWS * 512];
__device__ int   g_rolled[156];

__constant__ int c_sh[4] = {-3,-3, 3, 3};
__constant__ int c_sw[4] = {-3, 3,-3, 3};

// -------------------------- tf32 helpers ------------------------------------
__device__ __forceinline__ float tf32r(float x) {
    uint32_t u;
    asm("cvt.rna.tf32.f32 %0, %1;" : "=r"(u) : "f"(x));
    return __uint_as_float(u);
}

__device__ __forceinline__ void mma_tf32(float c[4], const uint32_t a[4],
                                         const uint32_t b[2]) {
    asm volatile(
        "mma.sync.aligned.m16n8k8.row.col.f32.tf32.tf32.f32 "
        "{%0,%1,%2,%3},{%4,%5,%6,%7},{%8,%9},{%0,%1,%2,%3};"
        : "+f"(c[0]), "+f"(c[1]), "+f"(c[2]), "+f"(c[3])
        : "r"(a[0]), "r"(a[1]), "r"(a[2]), "r"(a[3]), "r"(b[0]), "r"(b[1]));
}

// -------------------------- init rolled index table -------------------------
__global__ void init_rolled_kernel() {
    if (threadIdx.x == 0 && blockIdx.x == 0) {
        int cnt = 0;
        for (int idx = 0; idx < 256; idx++) {
            int m = idx >> 6, r = (idx >> 3) & 7, c = idx & 7;
            bool valid;
            if      (m == 0) valid = (r >= 5) || (c >= 5);
            else if (m == 1) valid = (r >= 5) || (c < 3);
            else if (m == 2) valid = (r < 3)  || (c >= 5);
            else             valid = (r < 3)  || (c < 3);
            if (valid) g_rolled[cnt++] = idx;
        }
    }
}

// -------------------------- layernorm (warp per row) -------------------------
__global__ void __launch_bounds__(256) ln_kernel(
    const float* __restrict__ x, const float* __restrict__ g,
    const float* __restrict__ b, float* __restrict__ out, int rows)
{
    int row = (blockIdx.x * blockDim.x + threadIdx.x) >> 5;
    if (row >= rows) return;
    int lane = threadIdx.x & 31;
    const float4* xr = (const float4*)(x + (size_t)row * CDIM);
    float4 v = xr[lane];
    float s = v.x + v.y + v.z + v.w;
    #pragma unroll
    for (int o = 16; o > 0; o >>= 1) s += __shfl_xor_sync(~0u, s, o);
    float mu = s * (1.0f / CDIM);
    float dx = v.x-mu, dy = v.y-mu, dz = v.z-mu, dw = v.w-mu;
    float s2 = dx*dx + dy*dy + dz*dz + dw*dw;
    #pragma unroll
    for (int o = 16; o > 0; o >>= 1) s2 += __shfl_xor_sync(~0u, s2, o);
    float rs = rsqrtf(s2 * (1.0f / CDIM) + 1e-5f);
    float4 gg = ((const float4*)g)[lane];
    float4 bb = ((const float4*)b)[lane];
    float4 o4;
    o4.x = dx*rs*gg.x + bb.x;
    o4.y = dy*rs*gg.y + bb.y;
    o4.z = dz*rs*gg.z + bb.z;
    o4.w = dw*rs*gg.w + bb.w;
    ((float4*)(out + (size_t)row * CDIM))[lane] = o4;
}

// -------------------------- tf32 GEMM: out = A @ W^T + bias (+epilogue) -----
// A:(M,K) rm, W:(N,K) rm. Block 128x64x32, 8 warps, warp 32x32 (2x4 m16n8k8).
// epi: 0=none, 1=exact gelu, 2=add residual
__global__ void __launch_bounds__(256) gemm_tc(
    const float* __restrict__ A, const float* __restrict__ W,
    const float* __restrict__ bias, const float* __restrict__ res,
    float* __restrict__ out, int M, int N, int K, int epi)
{
    __shared__ float As[128][36];
    __shared__ float Ws[64][36];
    int tid = threadIdx.x, lane = tid & 31, warp = tid >> 5;
    int wm = warp >> 1, wn = warp & 1;
    int grp = lane >> 2, tig = lane & 3;
    int m0 = blockIdx.y * 128, n0 = blockIdx.x * 64;

    float c[2][4][4];
    #pragma unroll
    for (int mt = 0; mt < 2; mt++)
        #pragma unroll
        for (int nt = 0; nt < 4; nt++)
            #pragma unroll
            for (int j = 0; j < 4; j++) c[mt][nt][j] = 0.f;

    for (int k0 = 0; k0 < K; k0 += 32) {
        #pragma unroll
        for (int i = 0; i < 4; i++) {
            int idx = tid + i * 256;
            int r = idx >> 3, cc = (idx & 7) * 4;
            float4 v = *(const float4*)&A[(size_t)(m0 + r) * K + k0 + cc];
            v.x = tf32r(v.x); v.y = tf32r(v.y); v.z = tf32r(v.z); v.w = tf32r(v.w);
            *(float4*)&As[r][cc] = v;
        }
        #pragma unroll
        for (int i = 0; i < 2; i++) {
            int idx = tid + i * 256;
            int r = idx >> 3, cc = (idx & 7) * 4;
            float4 v = *(const float4*)&W[(size_t)(n0 + r) * K + k0 + cc];
            v.x = tf32r(v.x); v.y = tf32r(v.y); v.z = tf32r(v.z); v.w = tf32r(v.w);
            *(float4*)&Ws[r][cc] = v;
        }
        __syncthreads();
        #pragma unroll
        for (int kk = 0; kk < 32; kk += 8) {
            uint32_t a[2][4], b[4][2];
            #pragma unroll
            for (int mt = 0; mt < 2; mt++) {
                int r0 = wm * 32 + mt * 16 + grp;
                a[mt][0] = __float_as_uint(As[r0    ][kk + tig]);
                a[mt][1] = __float_as_uint(As[r0 + 8][kk + tig]);
                a[mt][2] = __float_as_uint(As[r0    ][kk + tig + 4]);
                a[mt][3] = __float_as_uint(As[r0 + 8][kk + tig + 4]);
            }
            #pragma unroll
            for (int nt = 0; nt < 4; nt++) {
                int cn = wn * 32 + nt * 8 + grp;
                b[nt][0] = __float_as_uint(Ws[cn][kk + tig]);
                b[nt][1] = __float_as_uint(Ws[cn][kk + tig + 4]);
            }
            #pragma unroll
            for (int mt = 0; mt < 2; mt++)
                #pragma unroll
                for (int nt = 0; nt < 4; nt++)
                    mma_tf32(c[mt][nt], a[mt], b[nt]);
        }
        __syncthreads();
    }

    #pragma unroll
    for (int mt = 0; mt < 2; mt++) {
        int r0 = m0 + wm * 32 + mt * 16 + grp;
        #pragma unroll
        for (int nt = 0; nt < 4; nt++) {
            int cn = n0 + wn * 32 + nt * 8 + tig * 2;
            float2 bp = *(const float2*)&bias[cn];
            #pragma unroll
            for (int half = 0; half < 2; half++) {
                int row = r0 + half * 8;
                float v0 = c[mt][nt][half * 2 + 0] + bp.x;
                float v1 = c[mt][nt][half * 2 + 1] + bp.y;
                if (epi == 1) {
                    v0 = 0.5f * v0 * (1.0f + erff(v0 * 0.70710678118654752f));
                    v1 = 0.5f * v1 * (1.0f + erff(v1 * 0.70710678118654752f));
                } else if (epi == 2) {
                    float2 rr = *(const float2*)&res[(size_t)row * N + cn];
                    v0 += rr.x; v1 += rr.y;
                }
                *(float2*)&out[(size_t)row * N + cn] = make_float2(v0, v1);
            }
        }
    }
}

// -------------------------- window pooling ----------------------------------
__global__ void __launch_bounds__(128) pool_kernel(
    const float* __restrict__ xh, const float* __restrict__ pw,
    const float* __restrict__ pb, float* __restrict__ pooled)
{
    int w = blockIdx.x;
    int b = w >> 10, ij = w & 1023;
    int i = ij >> 5, j = ij & 31;
    int c = threadIdx.x;
    float acc = 0.f;
    #pragma unroll
    for (int n = 0; n < 64; n++) {
        int r = n >> 3, cc = n & 7;
        size_t tok = (size_t)(b * HW + (i * 8 + r) * 256 + (j * 8 + cc));
        acc += xh[tok * CDIM + c] * pw[n];
    }
    pooled[(size_t)w * CDIM + c] = acc + pb[0];
}

// -------------------------- attention bias ----------------------------------
__device__ __forceinline__ float attn_bias(
    int q, int k, int h, int wi, int wj,
    const float* __restrict__ rpbt, const float* __restrict__ rpbn,
    const float* __restrict__ rpbw)
{
    int qr = q >> 3, qc = q & 7;
    if (k < 64) {
        int kr = k >> 3, kc = k & 7;
        return rpbt[((qr - kr + 7) * 15 + (qc - kc + 7)) * HEADS + h];
    }
    if (k < NROLL) return rpbn[(size_t)(h * 64 + q) * 156 + (k - 64)];
    int p = k - NROLL;
    int kr = p / 3, kc = p % 3;
    float b = rpbw[h * 100 + (qr - kr + 2) * 10 + (qc - kc + 2)];
    int pi = wi + kr - 1, pj = wj + kc - 1;
    if (!(pi >= 0 && pi < 32 && pj >= 0 && pj < 32)) b -= 100.f;
    return b;
}

// -------------------------- attention (tf32 mma) -----------------------------
// grid (2048, 4), 512 threads (16 warps)
// smem: sQ[64][36] | sK[256][36] | sVt[32][260] | sAttn[64][260] | sInv[64]
__global__ void __launch_bounds__(512) attn_kernel(
    const float* __restrict__ qkv, const float* __restrict__ qkvp,
    const float* __restrict__ rpbt, const float* __restrict__ rpbn,
    const float* __restrict__ rpbw, float* __restrict__ out)
{
    extern __shared__ float sm[];
    float* sQ    = sm;                  // 64*36  = 2304
    float* sK    = sQ + 2304;           // 256*36 = 9216
    float* sVt   = sK + 9216;           // 32*260 = 8320
    float* sAttn = sVt + 8320;          // 64*260 = 16640
    float* sInv  = sAttn + 16640;       // 64

    int tid = threadIdx.x, lane = tid & 31, warp = tid >> 5;
    int grp = lane >> 2, tig = lane & 3;
    int w = blockIdx.x, h = blockIdx.y;
    int b = w >> 10, wi = (w >> 5) & 31, wj = w & 31;
    int bt = b << 16;

    // ---- load Q (scaled, tf32): sQ[q][d], stride 36 ----
    {
        int q = tid >> 3, d4 = (tid & 7) * 4;
        int gi = wi * 8 + (q >> 3), gj = wj * 8 + (q & 7);
        float4 v = *(const float4*)&qkv[(size_t)(bt + gi * 256 + gj) * 384 + h * 32 + d4];
        v.x = tf32r(v.x * SCALE); v.y = tf32r(v.y * SCALE);
        v.z = tf32r(v.z * SCALE); v.w = tf32r(v.w * SCALE);
        *(float4*)&sQ[q * 36 + d4] = v;
    }
    // ---- gather K (sK[kpos][d]) and V^T (sVt[d][kpos]); pad 229..255 zero ----
    #pragma unroll
    for (int it = 0; it < 4; it++) {
        int idx = tid + it * 512;           // 2048 slots: krow = idx>>3, d4=(idx&7)*4
        int krow = idx >> 3, d4 = (idx & 7) * 4;
        float4 kv = make_float4(0.f, 0.f, 0.f, 0.f);
        float4 vv = kv;
        if (krow < NROLL) {
            int gi, gj;
            if (krow < 64) {
                gi = wi * 8 + (krow >> 3);
                gj = wj * 8 + (krow & 7);
            } else {
                int raw = g_rolled[krow - 64];
                int m = raw >> 6, r = (raw >> 3) & 7, c = raw & 7;
                gi = (wi * 8 + r - c_sh[m]) & 255;
                gj = (wj * 8 + c - c_sw[m]) & 255;
            }
            size_t base = (size_t)(bt + gi * 256 + gj) * 384 + 128 + h * 32 + d4;
            kv = *(const float4*)&qkv[base];
            vv = *(const float4*)&qkv[base + 128];
        } else if (krow < NALL) {
            int p = krow - NROLL;
            int pi = wi + p / 3 - 1, pj = wj + p % 3 - 1;
            if (pi >= 0 && pi < 32 && pj >= 0 && pj < 32) {
                size_t base = (size_t)((b << 10) + pi * 32 + pj) * 384 + 128 + h * 32 + d4;
                kv = *(const float4*)&qkvp[base];
                vv = *(const float4*)&qkvp[base + 128];
            }
        }
        kv.x = tf32r(kv.x); kv.y = tf32r(kv.y); kv.z = tf32r(kv.z); kv.w = tf32r(kv.w);
        *(float4*)&sK[krow * 36 + d4] = kv;
        sVt[(d4 + 0) * LDP + krow] = tf32r(vv.x);
        sVt[(d4 + 1) * LDP + krow] = tf32r(vv.y);
        sVt[(d4 + 2) * LDP + krow] = tf32r(vv.z);
        sVt[(d4 + 3) * LDP + krow] = tf32r(vv.w);
    }
    __syncthreads();

    // ---- QK^T (tf32 mma): warp = (wm mtile, ng 8 ntiles) ----
    {
        int wm = warp >> 2, ng = warp & 3;
        float c[8][4];
        #pragma unroll
        for (int nt = 0; nt < 8; nt++)
            #pragma unroll
            for (int j = 0; j < 4; j++) c[nt][j] = 0.f;
        #pragma unroll
        for (int kk = 0; kk < 32; kk += 8) {
            uint32_t a[4];
            int r0 = wm * 16 + grp;
            a[0] = __float_as_uint(sQ[(r0    ) * 36 + kk + tig]);
            a[1] = __float_as_uint(sQ[(r0 + 8) * 36 + kk + tig]);
            a[2] = __float_as_uint(sQ[(r0    ) * 36 + kk + tig + 4]);
            a[3] = __float_as_uint(sQ[(r0 + 8) * 36 + kk + tig + 4]);
            #pragma unroll
            for (int nt = 0; nt < 8; nt++) {
                int n = ng * 64 + nt * 8 + grp;
                uint32_t bfr[2];
                bfr[0] = __float_as_uint(sK[n * 36 + kk + tig]);
                bfr[1] = __float_as_uint(sK[n * 36 + kk + tig + 4]);
                mma_tf32(c[nt], a, bfr);
            }
        }
        // epilogue: + bias, pads -> 0, store to sAttn
        int r0 = wm * 16 + grp;
        #pragma unroll
        for (int nt = 0; nt < 8; nt++) {
            int cn = ng * 64 + nt * 8 + tig * 2;
            #pragma unroll
            for (int half = 0; half < 2; half++) {
                int row = r0 + half * 8;
                int k0c = cn, k1c = cn + 1;
                float v0 = (k0c < NALL)
                    ? c[nt][half * 2 + 0] + attn_bias(row, k0c, h, wi, wj, rpbt, rpbn, rpbw)
                    : 0.f;
                float v1 = (k1c < NALL)
                    ? c[nt][half * 2 + 1] + attn_bias(row, k1c, h, wi, wj, rpbt, rpbn, rpbw)
                    : 0.f;
                sAttn[row * LDP + k0c] = v0;
                sAttn[row * LDP + k1c] = v1;
            }
        }
    }
    __syncthreads();

    // ---- softmax: 8 threads per row (cols < 229); pads stay 0 ----
    {
        int row = tid >> 3, l8 = tid & 7;
        float* pr = sAttn + row * LDP;
        float mx = -1e30f;
        for (int k = l8; k < NALL; k += 8) mx = fmaxf(mx, pr[k]);
        mx = fmaxf(mx, __shfl_xor_sync(~0u, mx, 1));
        mx = fmaxf(mx, __shfl_xor_sync(~0u, mx, 2));
        mx = fmaxf(mx, __shfl_xor_sync(~0u, mx, 4));
        float s = 0.f;
        for (int k = l8; k < NALL; k += 8) {
            float e = __expf(pr[k] - mx);
            pr[k] = tf32r(e);
            s += e;
        }
        s += __shfl_xor_sync(~0u, s, 1);
        s += __shfl_xor_sync(~0u, s, 2);
        s += __shfl_xor_sync(~0u, s, 4);
        if (l8 == 0) sInv[row] = 1.0f / s;
    }
    __syncthreads();

    // ---- P @ V (tf32 mma): warp = (wm mtile, wn ntile of 8 dims) ----
    {
        int wm = warp >> 2, wn = warp & 3;
        float c[4] = {0.f, 0.f, 0.f, 0.f};
        int r0 = wm * 16 + grp;
        int vn = wn * 8 + grp;
        #pragma unroll 8
        for (int kk = 0; kk < NPAD; kk += 8) {
            uint32_t a[4], bfr[2];
            a[0] = __float_as_uint(sAttn[(r0    ) * LDP + kk + tig]);
            a[1] = __float_as_uint(sAttn[(r0 + 8) * LDP + kk + tig]);
            a[2] = __float_as_uint(sAttn[(r0    ) * LDP + kk + tig + 4]);
            a[3] = __float_as_uint(sAttn[(r0 + 8) * LDP + kk + tig + 4]);
            bfr[0] = __float_as_uint(sVt[vn * LDP + kk + tig]);
            bfr[1] = __float_as_uint(sVt[vn * LDP + kk + tig + 4]);
            mma_tf32(c, a, bfr);
        }
        int d0 = wn * 8 + tig * 2;
        #pragma unroll
        for (int half = 0; half < 2; half++) {
            int row = r0 + half * 8;
            float inv = sInv[row];
            int gi = wi * 8 + (row >> 3), gj = wj * 8 + (row & 7);
            float* o = out + (size_t)(bt + gi * 256 + gj) * CDIM + h * 32 + d0;
            *(float2*)o = make_float2(c[half * 2 + 0] * inv, c[half * 2 + 1] * inv);
        }
    }
}

// ----------------------------------------------------------------------------
extern "C" void kernel_launch(void* const* d_in, const int* in_sizes, int n_in,
                              void* d_out, int out_size)
{
    const float* x      = (const float*)d_in[0];
    const float* qkv_w  = (const float*)d_in[1];
    const float* qkv_b  = (const float*)d_in[2];
    const float* proj_w = (const float*)d_in[3];
    const float* proj_b = (const float*)d_in[4];
    const float* n1g    = (const float*)d_in[5];
    const float* n1b    = (const float*)d_in[6];
    const float* n2g    = (const float*)d_in[7];
    const float* n2b    = (const float*)d_in[8];
    const float* rpbt   = (const float*)d_in[9];
    const float* rpbn   = (const float*)d_in[10];
    const float* rpbw   = (const float*)d_in[11];
    const float* poolw  = (const float*)d_in[12];
    const float* poolb  = (const float*)d_in[13];
    const float* fc1_w  = (const float*)d_in[14];
    const float* fc1_b  = (const float*)d_in[15];
    const float* fc2_w  = (const float*)d_in[16];
    const float* fc2_b  = (const float*)d_in[17];
    float* outp = (float*)d_out;

    float *p_xh, *p_qkv, *p_pooled, *p_qkvp, *p_attnout, *p_x2, *p_fc1;
    cudaGetSymbolAddress((void**)&p_xh, g_xh);
    cudaGetSymbolAddress((void**)&p_qkv, g_qkv);
    cudaGetSymbolAddress((void**)&p_pooled, g_pooled);
    cudaGetSymbolAddress((void**)&p_qkvp, g_qkvp);
    cudaGetSymbolAddress((void**)&p_attnout, g_attnout);
    cudaGetSymbolAddress((void**)&p_x2, g_x2);
    cudaGetSymbolAddress((void**)&p_fc1, g_fc1);

    const int ATTN_SMEM = (2304 + 9216 + 8320 + 16640 + 64) * 4;  // 146176 B
    cudaFuncSetAttribute(attn_kernel,
                         cudaFuncAttributeMaxDynamicSharedMemorySize, ATTN_SMEM);

    // 0. rolled index table
    init_rolled_kernel<<<1, 1>>>();
    // 1. LN1
    ln_kernel<<<MROWS / 8, 256>>>(x, n1g, n1b, p_xh, MROWS);
    // 2. qkv GEMM  (131072 x 384, K=128)
    gemm_tc<<<dim3(384 / 64, MROWS / 128), 256>>>(
        p_xh, qkv_w, qkv_b, nullptr, p_qkv, MROWS, 384, 128, 0);
    // 3. window pooling
    pool_kernel<<<BATCH * NWIN, 128>>>(p_xh, poolw, poolb, p_pooled);
    // 4. qkv of pooled (2048 x 384, K=128)
    gemm_tc<<<dim3(384 / 64, (BATCH * NWIN) / 128), 256>>>(
        p_pooled, qkv_w, qkv_b, nullptr, p_qkvp, BATCH * NWIN, 384, 128, 0);
    // 5. focal attention (tf32 mma)
    attn_kernel<<<dim3(BATCH * NWIN, HEADS), 512, ATTN_SMEM>>>(
        p_qkv, p_qkvp, rpbt, rpbn, rpbw, p_attnout);
    // 6. proj + residual(x)
    gemm_tc<<<dim3(CDIM / 64, MROWS / 128), 256>>>(
        p_attnout, proj_w, proj_b, x, p_x2, MROWS, CDIM, 128, 2);
    // 7. LN2
    ln_kernel<<<MROWS / 8, 256>>>(p_x2, n2g, n2b, p_xh, MROWS);
    // 8. fc1 + exact GELU (131072 x 512, K=128)
    gemm_tc<<<dim3(512 / 64, MROWS / 128), 256>>>(
        p_xh, fc1_w, fc1_b, nullptr, p_fc1, MROWS, 512, 128, 1);
    // 9. fc2 + residual(x2) -> out (131072 x 128, K=512)
    gemm_tc<<<dim3(CDIM / 64, MROWS / 128), 256>>>(
        p_fc1, fc2_w, fc2_b, p_x2, outp, MROWS, CDIM, 512, 2);
}

// round 6
// speedup vs baseline: 3.1018x; 1.2717x over previous
#include <cuda_runtime.h>
#include <cuda_bf16.h>
#include <cstdint>
#include <cstddef>

// ----------------------------------------------------------------------------
// FocalTransformerBlock  B=2, H=W=256, C=128, HEADS=4, HD=32, WS=8, EXP=3
// bf16 tensor-core version (mma.sync.m16n8k16), fp32 residual trunk
// ----------------------------------------------------------------------------

#define BATCH   2
#define HW      65536
#define CDIM    128
#define MROWS   (BATCH*HW)      // 131072
#define NWH     32
#define NWIN    1024
#define WA      64
#define NROLL   220
#define NALL    229
#define NPAD    256             // K-dim padded for mma
#define HEADS   4
#define HD      32
#define SCALE   0.17677669529663687f

typedef __nv_bfloat16 bf16;

// -------------------------- scratch (static device) -------------------------
__device__ bf16  g_xh[MROWS * CDIM];
__device__ bf16  g_qkv[MROWS * 3 * CDIM];
__device__ bf16  g_pooled[BATCH * NWIN * CDIM];
__device__ bf16  g_qkvp[BATCH * NWIN * 3 * CDIM];
__device__ bf16  g_attnout[MROWS * CDIM];
__device__ float g_x2[MROWS * CDIM];
__device__ bf16  g_fc1[MROWS * 512];
__device__ int   g_rolled[156];

__constant__ int c_sh[4] = {-3,-3, 3, 3};
__constant__ int c_sw[4] = {-3, 3,-3, 3};

// -------------------------- helpers -----------------------------------------
__device__ __forceinline__ uint32_t pack_bf2(float x, float y) {
    __nv_bfloat162 p = __floats2bfloat162_rn(x, y);
    return *reinterpret_cast<uint32_t*>(&p);
}

__device__ __forceinline__ void mma_bf16(float c[4], const uint32_t a[4],
                                         const uint32_t b[2]) {
    asm volatile(
        "mma.sync.aligned.m16n8k16.row.col.f32.bf16.bf16.f32 "
        "{%0,%1,%2,%3},{%4,%5,%6,%7},{%8,%9},{%0,%1,%2,%3};"
        : "+f"(c[0]), "+f"(c[1]), "+f"(c[2]), "+f"(c[3])
        : "r"(a[0]), "r"(a[1]), "r"(a[2]), "r"(a[3]), "r"(b[0]), "r"(b[1]));
}

// -------------------------- init rolled index table -------------------------
__global__ void init_rolled_kernel() {
    if (threadIdx.x == 0 && blockIdx.x == 0) {
        int cnt = 0;
        for (int idx = 0; idx < 256; idx++) {
            int m = idx >> 6, r = (idx >> 3) & 7, c = idx & 7;
            bool valid;
            if      (m == 0) valid = (r >= 5) || (c >= 5);
            else if (m == 1) valid = (r >= 5) || (c < 3);
            else if (m == 2) valid = (r < 3)  || (c >= 5);
            else             valid = (r < 3)  || (c < 3);
            if (valid) g_rolled[cnt++] = idx;
        }
    }
}

// -------------------------- layernorm (fp32 in -> bf16 out) ------------------
__global__ void __launch_bounds__(256) ln_kernel(
    const float* __restrict__ x, const float* __restrict__ g,
    const float* __restrict__ b, bf16* __restrict__ out, int rows)
{
    int row = (blockIdx.x * blockDim.x + threadIdx.x) >> 5;
    if (row >= rows) return;
    int lane = threadIdx.x & 31;
    const float4* xr = (const float4*)(x + (size_t)row * CDIM);
    float4 v = xr[lane];
    float s = v.x + v.y + v.z + v.w;
    #pragma unroll
    for (int o = 16; o > 0; o >>= 1) s += __shfl_xor_sync(~0u, s, o);
    float mu = s * (1.0f / CDIM);
    float dx = v.x-mu, dy = v.y-mu, dz = v.z-mu, dw = v.w-mu;
    float s2 = dx*dx + dy*dy + dz*dz + dw*dw;
    #pragma unroll
    for (int o = 16; o > 0; o >>= 1) s2 += __shfl_xor_sync(~0u, s2, o);
    float rs = rsqrtf(s2 * (1.0f / CDIM) + 1e-5f);
    float4 gg = ((const float4*)g)[lane];
    float4 bb = ((const float4*)b)[lane];
    uint2 o2;
    o2.x = pack_bf2(dx*rs*gg.x + bb.x, dy*rs*gg.y + bb.y);
    o2.y = pack_bf2(dz*rs*gg.z + bb.z, dw*rs*gg.w + bb.w);
    ((uint2*)(out + (size_t)row * CDIM))[lane] = o2;
}

// -------------------------- bf16 GEMM: out = A @ W^T + bias (+epilogue) -----
// A:(M,K) bf16 rm, W:(N,K) fp32 rm. Block 128x64x32, 8 warps, warp 32x32.
// epi: 0 = bf16 out, 1 = gelu -> bf16 out, 2 = +res(fp32) -> fp32 out
__global__ void __launch_bounds__(256) gemm_tc(
    const bf16* __restrict__ A, const float* __restrict__ W,
    const float* __restrict__ bias, const float* __restrict__ res,
    void* __restrict__ outv, int M, int N, int K, int epi)
{
    __shared__ uint32_t As[128][20];   // rows of 32 bf16 (16 u32), pad 20
    __shared__ uint32_t Ws[64][20];
    int tid = threadIdx.x, lane = tid & 31, warp = tid >> 5;
    int wm = warp >> 1, wn = warp & 1;
    int grp = lane >> 2, tig = lane & 3;
    int m0 = blockIdx.y * 128, n0 = blockIdx.x * 64;

    float c[2][4][4];
    #pragma unroll
    for (int mt = 0; mt < 2; mt++)
        #pragma unroll
        for (int nt = 0; nt < 4; nt++)
            #pragma unroll
            for (int j = 0; j < 4; j++) c[mt][nt][j] = 0.f;

    for (int k0 = 0; k0 < K; k0 += 32) {
        // A chunk: 128 rows x 32 bf16 -> 512 uint4 slots, 2 per thread
        #pragma unroll
        for (int i = 0; i < 2; i++) {
            int idx = tid + i * 256;
            int r = idx >> 2, c8 = (idx & 3) * 8;
            uint4 v = *(const uint4*)&A[(size_t)(m0 + r) * K + k0 + c8];
            *(uint4*)&As[r][c8 >> 1] = v;
        }
        // W chunk: 64 rows x 32 fp32 -> cvt bf16; 8 floats per thread
        #pragma unroll
        for (int i = 0; i < 2; i++) {
            int idx = tid + i * 256;
            int r = idx >> 3, c4 = (idx & 7) * 4;
            if (r < 64) {
                float4 v = *(const float4*)&W[(size_t)(n0 + r) * K + k0 + c4];
                Ws[r][(c4 >> 1)    ] = pack_bf2(v.x, v.y);
                Ws[r][(c4 >> 1) + 1] = pack_bf2(v.z, v.w);
            }
        }
        __syncthreads();
        #pragma unroll
        for (int ks = 0; ks < 2; ks++) {
            int base = ks * 8;
            uint32_t a[2][4], b[4][2];
            #pragma unroll
            for (int mt = 0; mt < 2; mt++) {
                int r0 = wm * 32 + mt * 16 + grp;
                a[mt][0] = As[r0    ][base + tig];
                a[mt][1] = As[r0 + 8][base + tig];
                a[mt][2] = As[r0    ][base + 4 + tig];
                a[mt][3] = As[r0 + 8][base + 4 + tig];
            }
            #pragma unroll
            for (int nt = 0; nt < 4; nt++) {
                int cn = wn * 32 + nt * 8 + grp;
                b[nt][0] = Ws[cn][base + tig];
                b[nt][1] = Ws[cn][base + 4 + tig];
            }
            #pragma unroll
            for (int mt = 0; mt < 2; mt++)
                #pragma unroll
                for (int nt = 0; nt < 4; nt++)
                    mma_bf16(c[mt][nt], a[mt], b[nt]);
        }
        __syncthreads();
    }

    #pragma unroll
    for (int mt = 0; mt < 2; mt++) {
        int r0 = m0 + wm * 32 + mt * 16 + grp;
        #pragma unroll
        for (int nt = 0; nt < 4; nt++) {
            int cn = n0 + wn * 32 + nt * 8 + tig * 2;
            float2 bp = *(const float2*)&bias[cn];
            #pragma unroll
            for (int half = 0; half < 2; half++) {
                int row = r0 + half * 8;
                float v0 = c[mt][nt][half * 2 + 0] + bp.x;
                float v1 = c[mt][nt][half * 2 + 1] + bp.y;
                if (epi == 1) {
                    v0 = 0.5f * v0 * (1.0f + erff(v0 * 0.70710678118654752f));
                    v1 = 0.5f * v1 * (1.0f + erff(v1 * 0.70710678118654752f));
                }
                if (epi == 2) {
                    float2 rr = *(const float2*)&res[(size_t)row * N + cn];
                    *(float2*)&((float*)outv)[(size_t)row * N + cn] =
                        make_float2(v0 + rr.x, v1 + rr.y);
                } else {
                    ((uint32_t*)outv)[((size_t)row * N + cn) >> 1] = pack_bf2(v0, v1);
                }
            }
        }
    }
}

// -------------------------- window pooling (bf16 in/out) ---------------------
__global__ void __launch_bounds__(128) pool_kernel(
    const bf16* __restrict__ xh, const float* __restrict__ pw,
    const float* __restrict__ pb, bf16* __restrict__ pooled)
{
    int w = blockIdx.x;
    int b = w >> 10, ij = w & 1023;
    int i = ij >> 5, j = ij & 31;
    int c = threadIdx.x;
    float acc = 0.f;
    #pragma unroll
    for (int n = 0; n < 64; n++) {
        int r = n >> 3, cc = n & 7;
        size_t tok = (size_t)(b * HW + (i * 8 + r) * 256 + (j * 8 + cc));
        acc += __bfloat162float(xh[tok * CDIM + c]) * pw[n];
    }
    pooled[(size_t)w * CDIM + c] = __float2bfloat16(acc + pb[0]);
}

// -------------------------- attention bias ----------------------------------
__device__ __forceinline__ float attn_bias(
    int q, int k, int h, int wi, int wj,
    const float* __restrict__ rpbt, const float* __restrict__ rpbn,
    const float* __restrict__ rpbw)
{
    int qr = q >> 3, qc = q & 7;
    if (k < 64) {
        int kr = k >> 3, kc = k & 7;
        return rpbt[((qr - kr + 7) * 15 + (qc - kc + 7)) * HEADS + h];
    }
    if (k < NROLL) return rpbn[(size_t)(h * 64 + q) * 156 + (k - 64)];
    int p = k - NROLL;
    int kr = p / 3, kc = p % 3;
    float b = rpbw[h * 100 + (qr - kr + 2) * 10 + (qc - kc + 2)];
    int pi = wi + kr - 1, pj = wj + kc - 1;
    if (!(pi >= 0 && pi < 32 && pj >= 0 && pj < 32)) b -= 100.f;
    return b;
}

// -------------------------- attention (bf16 mma) -----------------------------
// grid (2048, 4), 512 threads (16 warps)
#define LDS_F 260               // sAttn fp32 row stride
#define LDP_H 264               // sP / sVt bf16 row stride (132 u32)
__global__ void __launch_bounds__(512) attn_kernel(
    const bf16* __restrict__ qkv, const bf16* __restrict__ qkvp,
    const float* __restrict__ rpbt, const float* __restrict__ rpbn,
    const float* __restrict__ rpbw, bf16* __restrict__ out)
{
    extern __shared__ char smraw[];
    float*    sAttn = (float*)smraw;                        // 64*260*4 = 66560
    uint32_t* sQ    = (uint32_t*)(smraw + 66560);           // [64][20]  = 5120
    uint32_t* sK    = (uint32_t*)(smraw + 66560 + 5120);    // [256][20] = 20480
    bf16*     sVt   = (bf16*)(smraw + 92160);               // [32][264] = 16896
    bf16*     sP    = (bf16*)(smraw + 109056);              // [64][264] = 33792
    float*    sInv  = (float*)(smraw + 142848);             // 64*4

    int tid = threadIdx.x, lane = tid & 31, warp = tid >> 5;
    int grp = lane >> 2, tig = lane & 3;
    int w = blockIdx.x, h = blockIdx.y;
    int b = w >> 10, wi = (w >> 5) & 31, wj = w & 31;
    int bt = b << 16;

    // ---- load Q: sQ[q][d], rows of 32 bf16 pad 40 (20 u32) ----
    {
        int q = tid >> 3, d4 = (tid & 7) * 4;
        int gi = wi * 8 + (q >> 3), gj = wj * 8 + (q & 7);
        uint2 v = *(const uint2*)&qkv[(size_t)(bt + gi * 256 + gj) * 384 + h * 32 + d4];
        *(uint2*)&sQ[q * 20 + (d4 >> 1)] = v;
    }
    // ---- gather K (sK[kpos][d]) and V^T (sVt[d][kpos]); pads zero ----
    #pragma unroll
    for (int it = 0; it < 4; it++) {
        int idx = tid + it * 512;
        int krow = idx >> 3, d4 = (idx & 7) * 4;
        uint2 kv = make_uint2(0u, 0u), vv = kv;
        if (krow < NROLL) {
            int gi, gj;
            if (krow < 64) {
                gi = wi * 8 + (krow >> 3);
                gj = wj * 8 + (krow & 7);
            } else {
                int raw = g_rolled[krow - 64];
                int m = raw >> 6, r = (raw >> 3) & 7, c = raw & 7;
                gi = (wi * 8 + r - c_sh[m]) & 255;
                gj = (wj * 8 + c - c_sw[m]) & 255;
            }
            size_t base = (size_t)(bt + gi * 256 + gj) * 384 + 128 + h * 32 + d4;
            kv = *(const uint2*)&qkv[base];
            vv = *(const uint2*)&qkv[base + 128];
        } else if (krow < NALL) {
            int p = krow - NROLL;
            int pi = wi + p / 3 - 1, pj = wj + p % 3 - 1;
            if (pi >= 0 && pi < 32 && pj >= 0 && pj < 32) {
                size_t base = (size_t)((b << 10) + pi * 32 + pj) * 384 + 128 + h * 32 + d4;
                kv = *(const uint2*)&qkvp[base];
                vv = *(const uint2*)&qkvp[base + 128];
            }
        }
        *(uint2*)&sK[krow * 20 + (d4 >> 1)] = kv;
        __nv_bfloat162 v0 = *reinterpret_cast<__nv_bfloat162*>(&vv.x);
        __nv_bfloat162 v1 = *reinterpret_cast<__nv_bfloat162*>(&vv.y);
        sVt[(d4 + 0) * LDP_H + krow] = v0.x;
        sVt[(d4 + 1) * LDP_H + krow] = v0.y;
        sVt[(d4 + 2) * LDP_H + krow] = v1.x;
        sVt[(d4 + 3) * LDP_H + krow] = v1.y;
    }
    __syncthreads();

    // ---- QK^T (bf16 mma): warp = (wm mtile, ng group of 8 ntiles) ----
    {
        int wm = warp >> 2, ng = warp & 3;
        float c[8][4];
        #pragma unroll
        for (int nt = 0; nt < 8; nt++)
            #pragma unroll
            for (int j = 0; j < 4; j++) c[nt][j] = 0.f;
        #pragma unroll
        for (int ks = 0; ks < 2; ks++) {      // k = 32 -> two k16 steps
            int base = ks * 8;
            uint32_t a[4];
            int r0 = wm * 16 + grp;
            a[0] = sQ[(r0    ) * 20 + base + tig];
            a[1] = sQ[(r0 + 8) * 20 + base + tig];
            a[2] = sQ[(r0    ) * 20 + base + 4 + tig];
            a[3] = sQ[(r0 + 8) * 20 + base + 4 + tig];
            #pragma unroll
            for (int nt = 0; nt < 8; nt++) {
                int n = ng * 64 + nt * 8 + grp;
                uint32_t bfr[2];
                bfr[0] = sK[n * 20 + base + tig];
                bfr[1] = sK[n * 20 + base + 4 + tig];
                mma_bf16(c[nt], a, bfr);
            }
        }
        // epilogue: v = c*SCALE + bias; pads -> 0
        int r0 = wm * 16 + grp;
        #pragma unroll
        for (int nt = 0; nt < 8; nt++) {
            int cn = ng * 64 + nt * 8 + tig * 2;
            #pragma unroll
            for (int half = 0; half < 2; half++) {
                int row = r0 + half * 8;
                float v0 = (cn < NALL)
                    ? c[nt][half * 2 + 0] * SCALE + attn_bias(row, cn, h, wi, wj, rpbt, rpbn, rpbw)
                    : 0.f;
                float v1 = (cn + 1 < NALL)
                    ? c[nt][half * 2 + 1] * SCALE + attn_bias(row, cn + 1, h, wi, wj, rpbt, rpbn, rpbw)
                    : 0.f;
                sAttn[row * LDS_F + cn]     = v0;
                sAttn[row * LDS_F + cn + 1] = v1;
            }
        }
    }
    __syncthreads();

    // ---- softmax: 8 threads per row; write bf16 P; zero pads ----
    {
        int row = tid >> 3, l8 = tid & 7;
        const float* pr = sAttn + row * LDS_F;
        bf16* pp = sP + row * LDP_H;
        float mx = -1e30f;
        for (int k = l8; k < NALL; k += 8) mx = fmaxf(mx, pr[k]);
        mx = fmaxf(mx, __shfl_xor_sync(~0u, mx, 1));
        mx = fmaxf(mx, __shfl_xor_sync(~0u, mx, 2));
        mx = fmaxf(mx, __shfl_xor_sync(~0u, mx, 4));
        float s = 0.f;
        for (int k = l8; k < NALL; k += 8) {
            float e = __expf(pr[k] - mx);
            pp[k] = __float2bfloat16(e);
            s += e;
        }
        for (int k = NALL + l8; k < NPAD; k += 8) pp[k] = __float2bfloat16(0.f);
        s += __shfl_xor_sync(~0u, s, 1);
        s += __shfl_xor_sync(~0u, s, 2);
        s += __shfl_xor_sync(~0u, s, 4);
        if (l8 == 0) sInv[row] = 1.0f / s;
    }
    __syncthreads();

    // ---- P @ V (bf16 mma): warp = (wm mtile, wn group of 8 dims) ----
    {
        int wm = warp >> 2, wn = warp & 3;
        const uint32_t* sP32 = (const uint32_t*)sP;
        const uint32_t* sV32 = (const uint32_t*)sVt;
        float c[4] = {0.f, 0.f, 0.f, 0.f};
        int r0 = wm * 16 + grp;
        int vn = wn * 8 + grp;
        #pragma unroll 4
        for (int kk = 0; kk < NPAD; kk += 16) {
            int base = kk >> 1;
            uint32_t a[4], bfr[2];
            a[0] = sP32[(r0    ) * 132 + base + tig];
            a[1] = sP32[(r0 + 8) * 132 + base + tig];
            a[2] = sP32[(r0    ) * 132 + base + 4 + tig];
            a[3] = sP32[(r0 + 8) * 132 + base + 4 + tig];
            bfr[0] = sV32[vn * 132 + base + tig];
            bfr[1] = sV32[vn * 132 + base + 4 + tig];
            mma_bf16(c, a, bfr);
        }
        int d0 = wn * 8 + tig * 2;
        #pragma unroll
        for (int half = 0; half < 2; half++) {
            int row = r0 + half * 8;
            float inv = sInv[row];
            int gi = wi * 8 + (row >> 3), gj = wj * 8 + (row & 7);
            uint32_t* o = (uint32_t*)&out[(size_t)(bt + gi * 256 + gj) * CDIM + h * 32 + d0];
            *o = pack_bf2(c[half * 2 + 0] * inv, c[half * 2 + 1] * inv);
        }
    }
}

// ----------------------------------------------------------------------------
extern "C" void kernel_launch(void* const* d_in, const int* in_sizes, int n_in,
                              void* d_out, int out_size)
{
    const float* x      = (const float*)d_in[0];
    const float* qkv_w  = (const float*)d_in[1];
    const float* qkv_b  = (const float*)d_in[2];
    const float* proj_w = (const float*)d_in[3];
    const float* proj_b = (const float*)d_in[4];
    const float* n1g    = (const float*)d_in[5];
    const float* n1b    = (const float*)d_in[6];
    const float* n2g    = (const float*)d_in[7];
    const float* n2b    = (const float*)d_in[8];
    const float* rpbt   = (const float*)d_in[9];
    const float* rpbn   = (const float*)d_in[10];
    const float* rpbw   = (const float*)d_in[11];
    const float* poolw  = (const float*)d_in[12];
    const float* poolb  = (const float*)d_in[13];
    const float* fc1_w  = (const float*)d_in[14];
    const float* fc1_b  = (const float*)d_in[15];
    const float* fc2_w  = (const float*)d_in[16];
    const float* fc2_b  = (const float*)d_in[17];
    float* outp = (float*)d_out;

    bf16 *p_xh, *p_qkv, *p_pooled, *p_qkvp, *p_attnout, *p_fc1;
    float *p_x2;
    cudaGetSymbolAddress((void**)&p_xh, g_xh);
    cudaGetSymbolAddress((void**)&p_qkv, g_qkv);
    cudaGetSymbolAddress((void**)&p_pooled, g_pooled);
    cudaGetSymbolAddress((void**)&p_qkvp, g_qkvp);
    cudaGetSymbolAddress((void**)&p_attnout, g_attnout);
    cudaGetSymbolAddress((void**)&p_x2, g_x2);
    cudaGetSymbolAddress((void**)&p_fc1, g_fc1);

    const int ATTN_SMEM = 142848 + 256;   // 143104 B
    cudaFuncSetAttribute(attn_kernel,
                         cudaFuncAttributeMaxDynamicSharedMemorySize, ATTN_SMEM);

    // 0. rolled index table
    init_rolled_kernel<<<1, 1>>>();
    // 1. LN1 -> bf16 xh
    ln_kernel<<<MROWS / 8, 256>>>(x, n1g, n1b, p_xh, MROWS);
    // 2. qkv GEMM  (131072 x 384, K=128) -> bf16
    gemm_tc<<<dim3(384 / 64, MROWS / 128), 256>>>(
        p_xh, qkv_w, qkv_b, nullptr, p_qkv, MROWS, 384, 128, 0);
    // 3. window pooling
    pool_kernel<<<BATCH * NWIN, 128>>>(p_xh, poolw, poolb, p_pooled);
    // 4. qkv of pooled (2048 x 384, K=128) -> bf16
    gemm_tc<<<dim3(384 / 64, (BATCH * NWIN) / 128), 256>>>(
        p_pooled, qkv_w, qkv_b, nullptr, p_qkvp, BATCH * NWIN, 384, 128, 0);
    // 5. focal attention (bf16 mma) -> bf16 attnout
    attn_kernel<<<dim3(BATCH * NWIN, HEADS), 512, ATTN_SMEM>>>(
        p_qkv, p_qkvp, rpbt, rpbn, rpbw, p_attnout);
    // 6. proj + residual(x) -> fp32 x2
    gemm_tc<<<dim3(CDIM / 64, MROWS / 128), 256>>>(
        p_attnout, proj_w, proj_b, x, p_x2, MROWS, CDIM, 128, 2);
    // 7. LN2 -> bf16 xh
    ln_kernel<<<MROWS / 8, 256>>>(p_x2, n2g, n2b, p_xh, MROWS);
    // 8. fc1 + exact GELU (131072 x 512, K=128) -> bf16
    gemm_tc<<<dim3(512 / 64, MROWS / 128), 256>>>(
        p_xh, fc1_w, fc1_b, nullptr, p_fc1, MROWS, 512, 128, 1);
    // 9. fc2 + residual(x2) -> fp32 out (131072 x 128, K=512)
    gemm_tc<<<dim3(CDIM / 64, MROWS / 128), 256>>>(
        p_fc1, fc2_w, fc2_b, p_x2, outp, MROWS, CDIM, 512, 2);
}